// round 1
// baseline (speedup 1.0000x reference)
#include <cuda_runtime.h>
#include <cstdint>

#define NNODES 100000
#define NEDGES 1600000

// ---------------- scratch (static __device__ — allocation-free) ----------------
__device__ int   g_deg[NNODES];
__device__ int   g_rowptr[NNODES];
__device__ int   g_cursor[NNODES];
__device__ int   g_col[NEDGES];
__device__ int   g_bsum[512];
__device__ int   g_boff[512];
__device__ float g_m [NNODES * 128];
__device__ float g_h1[NNODES * 128];
__device__ float g_h2[NNODES * 128];
__device__ float g_h3[NNODES * 256];

// ---------------- CSR build ----------------
__global__ void k_zero_deg(int n) {
    int i = blockIdx.x * blockDim.x + threadIdx.x;
    if (i < n) g_deg[i] = 0;
}

__global__ void k_count(const int* __restrict__ dst, int E) {
    int e = blockIdx.x * blockDim.x + threadIdx.x;
    if (e < E) atomicAdd(&g_deg[dst[e]], 1);
}

// block-local exclusive scan of deg -> rowptr, block totals -> g_bsum
__global__ void k_scan1(int n) {
    int tid = threadIdx.x, lane = tid & 31, warp = tid >> 5;
    int i = blockIdx.x * 256 + tid;
    int v = (i < n) ? g_deg[i] : 0;
    int x = v;
    #pragma unroll
    for (int o = 1; o < 32; o <<= 1) {
        int t = __shfl_up_sync(0xffffffffu, x, o);
        if (lane >= o) x += t;
    }
    __shared__ int wq[8];
    if (lane == 31) wq[warp] = x;
    __syncthreads();
    if (warp == 0) {
        int y = (lane < 8) ? wq[lane] : 0;
        int z = y;
        #pragma unroll
        for (int o = 1; o < 8; o <<= 1) {
            int t = __shfl_up_sync(0xffffffffu, z, o);
            if (lane >= o) z += t;
        }
        if (lane < 8) wq[lane] = z - y;          // exclusive warp offset
        if (lane == 7) g_bsum[blockIdx.x] = z;   // block total
    }
    __syncthreads();
    if (i < n) g_rowptr[i] = wq[warp] + x - v;
}

// single-block exclusive scan of block totals (nb <= 512)
__global__ void k_scan2(int nb) {
    int tid = threadIdx.x, lane = tid & 31, warp = tid >> 5;
    int v = (tid < nb) ? g_bsum[tid] : 0;
    int x = v;
    #pragma unroll
    for (int o = 1; o < 32; o <<= 1) {
        int t = __shfl_up_sync(0xffffffffu, x, o);
        if (lane >= o) x += t;
    }
    __shared__ int wq[16];
    if (lane == 31) wq[warp] = x;
    __syncthreads();
    if (warp == 0) {
        int y = (lane < 16) ? wq[lane] : 0;
        int z = y;
        #pragma unroll
        for (int o = 1; o < 16; o <<= 1) {
            int t = __shfl_up_sync(0xffffffffu, z, o);
            if (lane >= o) z += t;
        }
        if (lane < 16) wq[lane] = z - y;
    }
    __syncthreads();
    if (tid < nb) g_boff[tid] = wq[warp] + x - v;
}

__global__ void k_scan3(int n) {
    int i = blockIdx.x * blockDim.x + threadIdx.x;
    if (i < n) {
        int r = g_rowptr[i] + g_boff[i >> 8];
        g_rowptr[i] = r;
        g_cursor[i] = r;
    }
}

__global__ void k_fill(const int* __restrict__ src, const int* __restrict__ dst, int E) {
    int e = blockIdx.x * blockDim.x + threadIdx.x;
    if (e < E) {
        int p = atomicAdd(&g_cursor[dst[e]], 1);
        g_col[p] = src[e];
    }
}

// ---------------- mean aggregation (CSR gather, warp per node) ----------------
template <int D>
__global__ void k_agg(const float* __restrict__ h, float* __restrict__ m, int n) {
    int gt = blockIdx.x * blockDim.x + threadIdx.x;
    int node = gt >> 5, lane = gt & 31;
    if (node >= n) return;
    const int R = D / 32;
    float acc[R];
    #pragma unroll
    for (int r = 0; r < R; r++) acc[r] = 0.0f;
    int s = g_rowptr[node], d = g_deg[node];
    int e = s, end = s + d;
    for (; e + 1 < end; e += 2) {
        int s0 = g_col[e], s1 = g_col[e + 1];
        const float* p0 = h + (size_t)s0 * D + lane;
        const float* p1 = h + (size_t)s1 * D + lane;
        #pragma unroll
        for (int r = 0; r < R; r++) { acc[r] += p0[r * 32]; acc[r] += p1[r * 32]; }
    }
    if (e < end) {
        int s0 = g_col[e];
        const float* p0 = h + (size_t)s0 * D + lane;
        #pragma unroll
        for (int r = 0; r < R; r++) acc[r] += p0[r * 32];
    }
    float inv = 1.0f / (float)(d > 0 ? d : 1);
    #pragma unroll
    for (int r = 0; r < R; r++) m[(size_t)node * D + r * 32 + lane] = acc[r] * inv;
}

// ---------------- packed f32x2 helpers (FFMA2 path) ----------------
__device__ __forceinline__ unsigned long long pkf2(float a) {
    unsigned long long r;
    unsigned int u = __float_as_uint(a);
    asm("mov.b64 %0, {%1, %1};" : "=l"(r) : "r"(u));
    return r;
}
__device__ __forceinline__ void fmaf2(unsigned long long& d, unsigned long long a, unsigned long long b) {
    asm("fma.rn.f32x2 %0, %1, %2, %0;" : "+l"(d) : "l"(a), "l"(b));
}
__device__ __forceinline__ float2 upf2(unsigned long long v) {
    unsigned int lo, hi;
    asm("mov.b64 {%0, %1}, %2;" : "=r"(lo), "=r"(hi) : "l"(v));
    return make_float2(__uint_as_float(lo), __uint_as_float(hi));
}

// ---------------- fused dual GEMM + bias + relu ----------------
// out = relu(A1 @ W1 + A2 @ W2 + bias), A* are [M,K], W* are [K,N]
// BM=128, BN=128, BK=16, 256 threads, 8x8 per thread (4x f32x2 cols)
template <int K, int N>
__global__ __launch_bounds__(256, 2) void k_gemm_dual(
    const float* __restrict__ A1, const float* __restrict__ A2,
    const float* __restrict__ W1, const float* __restrict__ W2,
    const float* __restrict__ bias, float* __restrict__ out, int M)
{
    __shared__ __align__(16) float As[16 * 132];
    __shared__ __align__(16) float Bs[16 * 128];
    int tid = threadIdx.x;
    int tx = tid & 15, ty = tid >> 4;
    int bm = blockIdx.y * 128;
    int bn = blockIdx.x * 128;

    unsigned long long acc[8][4];
    #pragma unroll
    for (int i = 0; i < 8; i++)
        #pragma unroll
        for (int j = 0; j < 4; j++) acc[i][j] = 0ull;

    for (int k0 = 0; k0 < 2 * K; k0 += 16) {
        const float* A = (k0 < K) ? A1 : A2;
        const float* W = (k0 < K) ? W1 : W2;
        int kb = (k0 < K) ? k0 : (k0 - K);

        // A tile: 128 rows x 16 k, transposed into As[k][m]
        #pragma unroll
        for (int q = 0; q < 2; q++) {
            int id = tid * 2 + q;
            int row = id >> 2, kc = id & 3;
            float4 v = make_float4(0.f, 0.f, 0.f, 0.f);
            int gr = bm + row;
            if (gr < M) v = *reinterpret_cast<const float4*>(A + (size_t)gr * K + kb + kc * 4);
            As[(kc * 4 + 0) * 132 + row] = v.x;
            As[(kc * 4 + 1) * 132 + row] = v.y;
            As[(kc * 4 + 2) * 132 + row] = v.z;
            As[(kc * 4 + 3) * 132 + row] = v.w;
        }
        // B tile: 16 k-rows x 128 n
        #pragma unroll
        for (int q = 0; q < 2; q++) {
            int id = tid * 2 + q;
            int kk = id >> 5, n4 = id & 31;
            *reinterpret_cast<float4*>(Bs + kk * 128 + n4 * 4) =
                *reinterpret_cast<const float4*>(W + (size_t)(kb + kk) * N + bn + n4 * 4);
        }
        __syncthreads();

        #pragma unroll
        for (int kk = 0; kk < 16; kk++) {
            const float4* As4 = reinterpret_cast<const float4*>(As + kk * 132);
            float4 a0 = As4[ty * 2], a1 = As4[ty * 2 + 1];
            const ulonglong2* Bs2 = reinterpret_cast<const ulonglong2*>(Bs + kk * 128);
            ulonglong2 b0 = Bs2[tx], b1 = Bs2[tx + 16];
            float av[8] = {a0.x, a0.y, a0.z, a0.w, a1.x, a1.y, a1.z, a1.w};
            #pragma unroll
            for (int i = 0; i < 8; i++) {
                unsigned long long pa = pkf2(av[i]);
                fmaf2(acc[i][0], pa, b0.x);
                fmaf2(acc[i][1], pa, b0.y);
                fmaf2(acc[i][2], pa, b1.x);
                fmaf2(acc[i][3], pa, b1.y);
            }
        }
        __syncthreads();
    }

    float4 bi0 = *reinterpret_cast<const float4*>(bias + bn + tx * 4);
    float4 bi1 = *reinterpret_cast<const float4*>(bias + bn + 64 + tx * 4);
    #pragma unroll
    for (int i = 0; i < 8; i++) {
        int gr = bm + ty * 8 + i;
        if (gr >= M) break;
        float2 p0 = upf2(acc[i][0]), p1 = upf2(acc[i][1]);
        float2 p2 = upf2(acc[i][2]), p3 = upf2(acc[i][3]);
        float4 o0 = make_float4(fmaxf(p0.x + bi0.x, 0.f), fmaxf(p0.y + bi0.y, 0.f),
                                fmaxf(p1.x + bi0.z, 0.f), fmaxf(p1.y + bi0.w, 0.f));
        float4 o1 = make_float4(fmaxf(p2.x + bi1.x, 0.f), fmaxf(p2.y + bi1.y, 0.f),
                                fmaxf(p3.x + bi1.z, 0.f), fmaxf(p3.y + bi1.w, 0.f));
        *reinterpret_cast<float4*>(out + (size_t)gr * N + bn + tx * 4) = o0;
        *reinterpret_cast<float4*>(out + (size_t)gr * N + bn + 64 + tx * 4) = o1;
    }
}

// ---------------- final FC: out = h3 @ Wfc + bfc  (256 -> 9), warp per node ----------------
__global__ void k_fc(const float* __restrict__ h, const float* __restrict__ W,
                     const float* __restrict__ b, float* __restrict__ out, int n) {
    __shared__ float sW[256 * 9];
    __shared__ float sb[9];
    for (int i = threadIdx.x; i < 256 * 9; i += blockDim.x) sW[i] = W[i];
    if (threadIdx.x < 9) sb[threadIdx.x] = b[threadIdx.x];
    __syncthreads();
    int warp = threadIdx.x >> 5, lane = threadIdx.x & 31;
    int node = blockIdx.x * 8 + warp;
    if (node >= n) return;
    float hv[8];
    #pragma unroll
    for (int r = 0; r < 8; r++) hv[r] = h[(size_t)node * 256 + r * 32 + lane];
    #pragma unroll
    for (int j = 0; j < 9; j++) {
        float s = 0.f;
        #pragma unroll
        for (int r = 0; r < 8; r++) s += hv[r] * sW[(r * 32 + lane) * 9 + j];
        #pragma unroll
        for (int o = 16; o > 0; o >>= 1) s += __shfl_xor_sync(0xffffffffu, s, o);
        if (lane == 0) out[node * 9 + j] = s + sb[j];
    }
}

// ---------------- launch ----------------
extern "C" void kernel_launch(void* const* d_in, const int* in_sizes, int n_in,
                              void* d_out, int out_size) {
    (void)n_in; (void)out_size;
    const float* x   = (const float*)d_in[0];
    const int*   ei  = (const int*)d_in[1];
    const float* Wl1 = (const float*)d_in[2];
    const float* bl1 = (const float*)d_in[3];
    const float* Wr1 = (const float*)d_in[4];
    const float* Wl2 = (const float*)d_in[5];
    const float* bl2 = (const float*)d_in[6];
    const float* Wr2 = (const float*)d_in[7];
    const float* Wl3 = (const float*)d_in[8];
    const float* bl3 = (const float*)d_in[9];
    const float* Wr3 = (const float*)d_in[10];
    const float* Wfc = (const float*)d_in[11];
    const float* bfc = (const float*)d_in[12];
    float* out = (float*)d_out;

    int M = in_sizes[0] / 64;
    int E = in_sizes[1] / 2;
    const int* src = ei;
    const int* dst = ei + E;

    float *pm, *ph1, *ph2, *ph3;
    cudaGetSymbolAddress((void**)&pm,  g_m);
    cudaGetSymbolAddress((void**)&ph1, g_h1);
    cudaGetSymbolAddress((void**)&ph2, g_h2);
    cudaGetSymbolAddress((void**)&ph3, g_h3);

    int nbN = (M + 255) / 256;          // 391
    int nbE = (E + 255) / 256;          // 6250
    int nbW = (M * 32 + 255) / 256;     // 12500 (warp per node)
    int gM  = (M + 127) / 128;          // 782

    // CSR build
    k_zero_deg<<<nbN, 256>>>(M);
    k_count<<<nbE, 256>>>(dst, E);
    k_scan1<<<nbN, 256>>>(M);
    k_scan2<<<1, 512>>>(nbN);
    k_scan3<<<nbN, 256>>>(M);
    k_fill<<<nbE, 256>>>(src, dst, E);

    // layer 1: d=64 -> 128
    k_agg<64><<<nbW, 256>>>(x, pm, M);
    k_gemm_dual<64, 128><<<dim3(1, gM), 256>>>(pm, x, Wl1, Wr1, bl1, ph1, M);

    // layer 2: 128 -> 128
    k_agg<128><<<nbW, 256>>>(ph1, pm, M);
    k_gemm_dual<128, 128><<<dim3(1, gM), 256>>>(pm, ph1, Wl2, Wr2, bl2, ph2, M);

    // layer 3: 128 -> 256
    k_agg<128><<<nbW, 256>>>(ph2, pm, M);
    k_gemm_dual<128, 256><<<dim3(2, gM), 256>>>(pm, ph2, Wl3, Wr3, bl3, ph3, M);

    // FC head: 256 -> 9
    k_fc<<<(M + 7) / 8, 256>>>(ph3, Wfc, bfc, out, M);
}

// round 4
// speedup vs baseline: 1.4958x; 1.4958x over previous
#include <cuda_runtime.h>
#include <cuda_bf16.h>
#include <cstdint>

#define NNODES 100000
#define NEDGES 1600000

// ---------------- scratch (static __device__ — allocation-free) ----------------
__device__ int g_deg[NNODES], g_rowptr[NNODES], g_cursor[NNODES], g_col[NEDGES];
__device__ int g_bsum[512], g_boff[512];
__device__ float g_m [NNODES * 128];
__device__ float g_h1[NNODES * 128];
__device__ float g_h2[NNODES * 128];
__device__ float g_h3[NNODES * 256];
__device__ float g_wt[256 * 256];

// ---------------- helpers ----------------
__device__ __forceinline__ uint32_t sw128(uint32_t b) { return b ^ ((b >> 3) & 0x70); }
__device__ __forceinline__ uint32_t cvta_smem(const void* p) {
    uint32_t a;
    asm("{ .reg .u64 t; cvta.to.shared.u64 t, %1; cvt.u32.u64 %0, t; }" : "=r"(a) : "l"(p));
    return a;
}
__device__ __forceinline__ void ldsm4(uint32_t& r0, uint32_t& r1, uint32_t& r2, uint32_t& r3,
                                      uint32_t addr) {
    asm volatile("ldmatrix.sync.aligned.m8n8.x4.shared.b16 {%0,%1,%2,%3}, [%4];"
                 : "=r"(r0), "=r"(r1), "=r"(r2), "=r"(r3) : "r"(addr));
}
__device__ __forceinline__ void mma16816(float* c, const uint32_t* a, uint32_t b0, uint32_t b1) {
    asm volatile(
        "mma.sync.aligned.m16n8k16.row.col.f32.bf16.bf16.f32 "
        "{%0,%1,%2,%3}, {%4,%5,%6,%7}, {%8,%9}, {%0,%1,%2,%3};"
        : "+f"(c[0]), "+f"(c[1]), "+f"(c[2]), "+f"(c[3])
        : "r"(a[0]), "r"(a[1]), "r"(a[2]), "r"(a[3]), "r"(b0), "r"(b1));
}
// split 4 fp32 -> 4 bf16 hi (8B) + 4 bf16 lo (8B)
__device__ __forceinline__ void split4(float4 v, uint2& H, uint2& L) {
    __nv_bfloat16 h0 = __float2bfloat16(v.x), h1 = __float2bfloat16(v.y);
    __nv_bfloat16 h2 = __float2bfloat16(v.z), h3 = __float2bfloat16(v.w);
    __nv_bfloat16 l0 = __float2bfloat16(v.x - __bfloat162float(h0));
    __nv_bfloat16 l1 = __float2bfloat16(v.y - __bfloat162float(h1));
    __nv_bfloat16 l2 = __float2bfloat16(v.z - __bfloat162float(h2));
    __nv_bfloat16 l3 = __float2bfloat16(v.w - __bfloat162float(h3));
    __nv_bfloat162 ph0 = __halves2bfloat162(h0, h1), ph1 = __halves2bfloat162(h2, h3);
    __nv_bfloat162 pl0 = __halves2bfloat162(l0, l1), pl1 = __halves2bfloat162(l2, l3);
    H = make_uint2(*(uint32_t*)&ph0, *(uint32_t*)&ph1);
    L = make_uint2(*(uint32_t*)&pl0, *(uint32_t*)&pl1);
}

// ---------------- CSR build ----------------
__global__ void k_zero_deg(int n) {
    int i = blockIdx.x * blockDim.x + threadIdx.x;
    if (i < n) g_deg[i] = 0;
}
__global__ void k_count(const int* __restrict__ dst, int E) {
    int e = blockIdx.x * blockDim.x + threadIdx.x;
    if (e < E) atomicAdd(&g_deg[dst[e]], 1);
}
__global__ void k_scan1(int n) {
    int tid = threadIdx.x, lane = tid & 31, warp = tid >> 5;
    int i = blockIdx.x * 256 + tid;
    int v = (i < n) ? g_deg[i] : 0;
    int x = v;
    #pragma unroll
    for (int o = 1; o < 32; o <<= 1) {
        int t = __shfl_up_sync(0xffffffffu, x, o);
        if (lane >= o) x += t;
    }
    __shared__ int wq[8];
    if (lane == 31) wq[warp] = x;
    __syncthreads();
    if (warp == 0) {
        int y = (lane < 8) ? wq[lane] : 0;
        int z = y;
        #pragma unroll
        for (int o = 1; o < 8; o <<= 1) {
            int t = __shfl_up_sync(0xffffffffu, z, o);
            if (lane >= o) z += t;
        }
        if (lane < 8) wq[lane] = z - y;
        if (lane == 7) g_bsum[blockIdx.x] = z;
    }
    __syncthreads();
    if (i < n) g_rowptr[i] = wq[warp] + x - v;
}
__global__ void k_scan2(int nb) {
    int tid = threadIdx.x, lane = tid & 31, warp = tid >> 5;
    int v = (tid < nb) ? g_bsum[tid] : 0;
    int x = v;
    #pragma unroll
    for (int o = 1; o < 32; o <<= 1) {
        int t = __shfl_up_sync(0xffffffffu, x, o);
        if (lane >= o) x += t;
    }
    __shared__ int wq[16];
    if (lane == 31) wq[warp] = x;
    __syncthreads();
    if (warp == 0) {
        int y = (lane < 16) ? wq[lane] : 0;
        int z = y;
        #pragma unroll
        for (int o = 1; o < 16; o <<= 1) {
            int t = __shfl_up_sync(0xffffffffu, z, o);
            if (lane >= o) z += t;
        }
        if (lane < 16) wq[lane] = z - y;
    }
    __syncthreads();
    if (tid < nb) g_boff[tid] = wq[warp] + x - v;
}
__global__ void k_scan3(int n) {
    int i = blockIdx.x * blockDim.x + threadIdx.x;
    if (i < n) {
        int r = g_rowptr[i] + g_boff[i >> 8];
        g_rowptr[i] = r;
        g_cursor[i] = r;
    }
}
__global__ void k_fill(const int* __restrict__ src, const int* __restrict__ dst, int E) {
    int e = blockIdx.x * blockDim.x + threadIdx.x;
    if (e < E) {
        int p = atomicAdd(&g_cursor[dst[e]], 1);
        g_col[p] = src[e];
    }
}

// ---------------- weight prep: g_wt[n][k] = (k<K1 ? Wl[k][n] : Wr[k-K1][n]) ----------------
__global__ void k_prep_w(const float* __restrict__ Wl, const float* __restrict__ Wr,
                         int K1, int KT, int N) {
    int i = blockIdx.x * blockDim.x + threadIdx.x;
    if (i >= N * KT) return;
    int n = i / KT, k = i % KT;
    g_wt[n * KT + k] = (k < K1) ? Wl[k * N + n] : Wr[(k - K1) * N + n];
}

// ---------------- mean aggregation (CSR gather, warp per node) ----------------
template <int D>
__global__ void k_agg(const float* __restrict__ h, float* __restrict__ m, int n) {
    int gt = blockIdx.x * blockDim.x + threadIdx.x;
    int node = gt >> 5, lane = gt & 31;
    if (node >= n) return;
    const int R = D / 32;
    float acc[R];
    #pragma unroll
    for (int r = 0; r < R; r++) acc[r] = 0.0f;
    int s = g_rowptr[node], d = g_deg[node];
    int e = s, end = s + d;
    for (; e + 1 < end; e += 2) {
        int s0 = g_col[e], s1 = g_col[e + 1];
        const float* p0 = h + (size_t)s0 * D + lane;
        const float* p1 = h + (size_t)s1 * D + lane;
        #pragma unroll
        for (int r = 0; r < R; r++) { acc[r] += p0[r * 32]; acc[r] += p1[r * 32]; }
    }
    if (e < end) {
        int s0 = g_col[e];
        const float* p0 = h + (size_t)s0 * D + lane;
        #pragma unroll
        for (int r = 0; r < R; r++) acc[r] += p0[r * 32];
    }
    float inv = 1.0f / (float)(d > 0 ? d : 1);
    #pragma unroll
    for (int r = 0; r < R; r++) m[(size_t)node * D + r * 32 + lane] = acc[r] * inv;
}

// ---------------- HMMA split-bf16 GEMM: out = relu([A1|A2] @ Wt^T + bias) ----------------
// A1:[M,K1] A2:[M,K2] fp32; Wt:[NT, KT] fp32 (g_wt); out:[M,NT] fp32.
// CTA 128x128, 8 warps (2m x 4n), warp tile 64x32, K-chunk 64. smem 64KB, 2 CTAs/SM.
#define SM_AH 0
#define SM_AL 16384
#define SM_WH 32768
#define SM_WL 49152
#define SM_TOT 65536

template <int K1, int K2, int NT>
__global__ void __launch_bounds__(256, 2) k_gemm_mma(
    const float* __restrict__ A1, const float* __restrict__ A2,
    const float* __restrict__ Wt, const float* __restrict__ bias,
    float* __restrict__ out, int M)
{
    extern __shared__ char smem[];
    constexpr int KT = K1 + K2;
    constexpr int NC = KT / 64;
    uint32_t sb = cvta_smem(smem);
    int tid = threadIdx.x, lane = tid & 31, wid = tid >> 5;
    int wm = wid & 1, wn = wid >> 1;           // 2 x 4 warp grid
    int bm = blockIdx.y * 128, bn = blockIdx.x * 128;

    float acc[4][4][4];
    #pragma unroll
    for (int mt = 0; mt < 4; mt++)
        #pragma unroll
        for (int nt = 0; nt < 4; nt++)
            #pragma unroll
            for (int j = 0; j < 4; j++) acc[mt][nt][j] = 0.f;

    // per-lane ldmatrix address components (x4, non-trans)
    int ar = lane & 15, ak = (lane >> 4) * 16;             // A: row, k-byte
    int nr = (lane & 7) + ((lane >> 4) << 3);              // W: n-row
    int nk = ((lane >> 3) & 1) * 16;                       // W: k-byte

    for (int c = 0; c < NC; c++) {
        const float* A; int Ks, kb;
        if (c * 64 < K1) { A = A1; Ks = K1; kb = c * 64; }
        else             { A = A2; Ks = K2; kb = c * 64 - K1; }

        // fill A tiles (hi/lo), 128 rows x 64 k
        #pragma unroll
        for (int p = 0; p < 8; p++) {
            int id = tid + p * 256;
            int row = id >> 4, kc = id & 15;
            int gr = bm + row;
            float4 v = make_float4(0.f, 0.f, 0.f, 0.f);
            if (gr < M) v = *(const float4*)(A + (size_t)gr * Ks + kb + kc * 4);
            uint2 H, L; split4(v, H, L);
            uint32_t so = sw128((uint32_t)(row * 128 + kc * 8));
            *(uint2*)(smem + SM_AH + so) = H;
            *(uint2*)(smem + SM_AL + so) = L;
        }
        // fill W tiles (hi/lo), 128 n-rows x 64 k
        #pragma unroll
        for (int p = 0; p < 8; p++) {
            int id = tid + p * 256;
            int row = id >> 4, kc = id & 15;
            float4 v = *(const float4*)(Wt + (size_t)(bn + row) * KT + c * 64 + kc * 4);
            uint2 H, L; split4(v, H, L);
            uint32_t so = sw128((uint32_t)(row * 128 + kc * 8));
            *(uint2*)(smem + SM_WH + so) = H;
            *(uint2*)(smem + SM_WL + so) = L;
        }
        __syncthreads();

        #pragma unroll
        for (int kk = 0; kk < 4; kk++) {
            uint32_t Ah[4][4], Al[4][4], Wh[4][2], Wl[4][2];
            #pragma unroll
            for (int mt = 0; mt < 4; mt++) {
                uint32_t off = sw128((uint32_t)((wm * 64 + mt * 16 + ar) * 128 + ak + kk * 32));
                ldsm4(Ah[mt][0], Ah[mt][1], Ah[mt][2], Ah[mt][3], sb + SM_AH + off);
            }
            #pragma unroll
            for (int h2 = 0; h2 < 2; h2++) {
                uint32_t off = sw128((uint32_t)((wn * 32 + h2 * 16 + nr) * 128 + nk + kk * 32));
                ldsm4(Wh[h2 * 2][0], Wh[h2 * 2][1], Wh[h2 * 2 + 1][0], Wh[h2 * 2 + 1][1],
                      sb + SM_WH + off);
            }
            #pragma unroll
            for (int mt = 0; mt < 4; mt++)
                #pragma unroll
                for (int nt = 0; nt < 4; nt++)
                    mma16816(acc[mt][nt], Ah[mt], Wh[nt][0], Wh[nt][1]);
            // lo(A) x hi(W)
            #pragma unroll
            for (int mt = 0; mt < 4; mt++) {
                uint32_t off = sw128((uint32_t)((wm * 64 + mt * 16 + ar) * 128 + ak + kk * 32));
                ldsm4(Al[mt][0], Al[mt][1], Al[mt][2], Al[mt][3], sb + SM_AL + off);
            }
            #pragma unroll
            for (int mt = 0; mt < 4; mt++)
                #pragma unroll
                for (int nt = 0; nt < 4; nt++)
                    mma16816(acc[mt][nt], Al[mt], Wh[nt][0], Wh[nt][1]);
            // hi(A) x lo(W)
            #pragma unroll
            for (int h2 = 0; h2 < 2; h2++) {
                uint32_t off = sw128((uint32_t)((wn * 32 + h2 * 16 + nr) * 128 + nk + kk * 32));
                ldsm4(Wl[h2 * 2][0], Wl[h2 * 2][1], Wl[h2 * 2 + 1][0], Wl[h2 * 2 + 1][1],
                      sb + SM_WL + off);
            }
            #pragma unroll
            for (int mt = 0; mt < 4; mt++)
                #pragma unroll
                for (int nt = 0; nt < 4; nt++)
                    mma16816(acc[mt][nt], Ah[mt], Wl[nt][0], Wl[nt][1]);
        }
        __syncthreads();
    }

    // epilogue: bias + relu, fp32 store
    int g = lane >> 2, t = lane & 3;
    #pragma unroll
    for (int nt = 0; nt < 4; nt++) {
        int col = bn + wn * 32 + nt * 8 + 2 * t;
        float2 bv = *(const float2*)(bias + col);
        #pragma unroll
        for (int mt = 0; mt < 4; mt++) {
            int r0 = bm + wm * 64 + mt * 16 + g;
            int r1 = r0 + 8;
            if (r0 < M) {
                float2 w = make_float2(fmaxf(acc[mt][nt][0] + bv.x, 0.f),
                                       fmaxf(acc[mt][nt][1] + bv.y, 0.f));
                *(float2*)(out + (size_t)r0 * NT + col) = w;
            }
            if (r1 < M) {
                float2 w = make_float2(fmaxf(acc[mt][nt][2] + bv.x, 0.f),
                                       fmaxf(acc[mt][nt][3] + bv.y, 0.f));
                *(float2*)(out + (size_t)r1 * NT + col) = w;
            }
        }
    }
}

// ---------------- final FC: out = h3 @ Wfc + bfc  (256 -> 9), warp per node ----------------
__global__ void k_fc(const float* __restrict__ h, const float* __restrict__ W,
                     const float* __restrict__ b, float* __restrict__ out, int n) {
    __shared__ float sW[256 * 9];
    __shared__ float sb[9];
    for (int i = threadIdx.x; i < 256 * 9; i += blockDim.x) sW[i] = W[i];
    if (threadIdx.x < 9) sb[threadIdx.x] = b[threadIdx.x];
    __syncthreads();
    int warp = threadIdx.x >> 5, lane = threadIdx.x & 31;
    int node = blockIdx.x * 8 + warp;
    if (node >= n) return;
    float hv[8];
    #pragma unroll
    for (int r = 0; r < 8; r++) hv[r] = h[(size_t)node * 256 + r * 32 + lane];
    #pragma unroll
    for (int j = 0; j < 9; j++) {
        float s = 0.f;
        #pragma unroll
        for (int r = 0; r < 8; r++) s += hv[r] * sW[(r * 32 + lane) * 9 + j];
        #pragma unroll
        for (int o = 16; o > 0; o >>= 1) s += __shfl_xor_sync(0xffffffffu, s, o);
        if (lane == 0) out[node * 9 + j] = s + sb[j];
    }
}

// ---------------- launch ----------------
extern "C" void kernel_launch(void* const* d_in, const int* in_sizes, int n_in,
                              void* d_out, int out_size) {
    (void)n_in; (void)out_size;
    const float* x   = (const float*)d_in[0];
    const int*   ei  = (const int*)d_in[1];
    const float* Wl1 = (const float*)d_in[2];
    const float* bl1 = (const float*)d_in[3];
    const float* Wr1 = (const float*)d_in[4];
    const float* Wl2 = (const float*)d_in[5];
    const float* bl2 = (const float*)d_in[6];
    const float* Wr2 = (const float*)d_in[7];
    const float* Wl3 = (const float*)d_in[8];
    const float* bl3 = (const float*)d_in[9];
    const float* Wr3 = (const float*)d_in[10];
    const float* Wfc = (const float*)d_in[11];
    const float* bfc = (const float*)d_in[12];
    float* out = (float*)d_out;

    int M = in_sizes[0] / 64;
    int E = in_sizes[1] / 2;
    const int* src = ei;
    const int* dst = ei + E;

    float *pm, *ph1, *ph2, *ph3, *pwt;
    cudaGetSymbolAddress((void**)&pm,  g_m);
    cudaGetSymbolAddress((void**)&ph1, g_h1);
    cudaGetSymbolAddress((void**)&ph2, g_h2);
    cudaGetSymbolAddress((void**)&ph3, g_h3);
    cudaGetSymbolAddress((void**)&pwt, g_wt);

    cudaFuncSetAttribute(k_gemm_mma<64, 64, 128>,
                         cudaFuncAttributeMaxDynamicSharedMemorySize, SM_TOT);
    cudaFuncSetAttribute(k_gemm_mma<128, 128, 128>,
                         cudaFuncAttributeMaxDynamicSharedMemorySize, SM_TOT);
    cudaFuncSetAttribute(k_gemm_mma<128, 128, 256>,
                         cudaFuncAttributeMaxDynamicSharedMemorySize, SM_TOT);

    int nbN = (M + 255) / 256;
    int nbE = (E + 255) / 256;
    int nbW = (M * 32 + 255) / 256;   // warp per node
    int gM  = (M + 127) / 128;        // 782

    // CSR build
    k_zero_deg<<<nbN, 256>>>(M);
    k_count<<<nbE, 256>>>(dst, E);
    k_scan1<<<nbN, 256>>>(M);
    k_scan2<<<1, 512>>>(nbN);
    k_scan3<<<nbN, 256>>>(M);
    k_fill<<<nbE, 256>>>(src, dst, E);

    // ---- layer 1: 64 -> 128 ----
    k_prep_w<<<(128 * 128 + 255) / 256, 256>>>(Wl1, Wr1, 64, 128, 128);
    k_agg<64><<<nbW, 256>>>(x, pm, M);
    k_gemm_mma<64, 64, 128><<<dim3(1, gM), 256, SM_TOT>>>(pm, x, pwt, bl1, ph1, M);

    // ---- layer 2: 128 -> 128 ----
    k_prep_w<<<(128 * 256 + 255) / 256, 256>>>(Wl2, Wr2, 128, 256, 128);
    k_agg<128><<<nbW, 256>>>(ph1, pm, M);
    k_gemm_mma<128, 128, 128><<<dim3(1, gM), 256, SM_TOT>>>(pm, ph1, pwt, bl2, ph2, M);

    // ---- layer 3: 128 -> 256 ----
    k_prep_w<<<(256 * 256 + 255) / 256, 256>>>(Wl3, Wr3, 128, 256, 256);
    k_agg<128><<<nbW, 256>>>(ph2, pm, M);
    k_gemm_mma<128, 128, 256><<<dim3(2, gM), 256, SM_TOT>>>(pm, ph2, pwt, bl3, ph3, M);

    // ---- FC head: 256 -> 9 ----
    k_fc<<<(M + 7) / 8, 256>>>(ph3, Wfc, bfc, out, M);
}